// round 1
// baseline (speedup 1.0000x reference)
#include <cuda_runtime.h>
#include <math.h>

// Problem: B=64 batches, per batch N=Q*C=400000 fp32 logits.
// Output (float32, concatenated): scores[B*K], labels[B*K], segments[B*K*2], query_ids[B*K].
//
// Strategy:
//   Kernel 1 (k_zero):    reset per-batch candidate counters.
//   Kernel 2 (k_collect): ONE streaming pass over all logits (102 MB). Values with
//                         logit > 2.8 (superset of top-100 with astronomical certainty
//                         for N(0,1) data) are pushed as 64-bit keys
//                         key = (bits(sigmoid(x)) << 32) | ~flat_idx
//                         into a per-batch global buffer via warp-aggregated atomics.
//                         Key ordering == jax.lax.top_k(prob) ordering (desc value,
//                         asc index tiebreak), since sigmoid>0 so its fp32 bits order
//                         as unsigned ints.
//   Kernel 3 (k_select):  one CTA per batch: exact MSD radix-select (8 x 8-bit digits)
//                         for the K-th largest key among candidates (L2-resident),
//                         collect exactly K winners (keys unique), rank by comparison,
//                         compute outputs. Exact slow-path fallback re-derives keys
//                         from global logits if the candidate set is unusable.

#define MAXB    64
#define CAP     16384
#define SLICES  16
#define TPB     256
#define KMAX    128

__device__ unsigned long long g_cand[MAXB * CAP];
__device__ int g_cnt[MAXB];

__device__ __forceinline__ float sigmoidf_(float x) {
    return 1.0f / (1.0f + expf(-x));
}

__device__ __forceinline__ unsigned long long make_key(float x, unsigned idx) {
    float s = sigmoidf_(x);
    return ((unsigned long long)__float_as_uint(s) << 32) | (unsigned long long)(~idx);
}

__global__ void k_zero(int B) {
    int i = threadIdx.x;
    if (i < B) g_cnt[i] = 0;
}

__global__ void k_collect(const float* __restrict__ logits, int N, float thresh, int per_cta) {
    int b = blockIdx.y;
    int start = blockIdx.x * per_cta;
    if (start >= N) return;
    int count = min(per_cta, N - start);
    const float* base = logits + (long long)b * N + start;
    int lane = threadIdx.x & 31;

    int n4 = count >> 2;
    const float4* p4 = (const float4*)base;   // base offsets are multiples of 4 elems
    for (int i = threadIdx.x; i < n4; i += blockDim.x) {
        float4 v = p4[i];
        #pragma unroll
        for (int j = 0; j < 4; j++) {
            float x = (j == 0) ? v.x : (j == 1) ? v.y : (j == 2) ? v.z : v.w;
            bool pred = x > thresh;
            unsigned m = __ballot_sync(0xffffffffu, pred);
            if (m) {
                int leader = __ffs(m) - 1;
                int basepos = 0;
                if (lane == leader) basepos = atomicAdd(&g_cnt[b], __popc(m));
                basepos = __shfl_sync(0xffffffffu, basepos, leader);
                if (pred) {
                    int my = basepos + __popc(m & ((1u << lane) - 1u));
                    if (my < CAP) {
                        unsigned idx = (unsigned)(start + 4 * i + j);
                        g_cand[b * CAP + my] = make_key(x, idx);
                    }
                }
            }
        }
    }
    // tail (<4 elems, only if N % 4 != 0 for a slice): thread 0 handles serially
    int tail = count & 3;
    if (tail && threadIdx.x == 0) {
        for (int t = 0; t < tail; t++) {
            float x = base[(n4 << 2) + t];
            if (x > thresh) {
                int p = atomicAdd(&g_cnt[b], 1);
                if (p < CAP) {
                    unsigned idx = (unsigned)(start + (n4 << 2) + t);
                    g_cand[b * CAP + p] = make_key(x, idx);
                }
            }
        }
    }
}

__global__ void k_select(const float* __restrict__ logits,
                         const float* __restrict__ segs,
                         const float* __restrict__ ts,
                         float* __restrict__ out,
                         int B, int Q, int C, int K) {
    int b = blockIdx.x;
    int N = Q * C;
    int tid = threadIdx.x;
    int cnt = g_cnt[b];
    bool slow = (cnt < K) || (cnt > CAP);   // exact fallback path (never taken for Gaussian data)
    int M = slow ? N : cnt;
    const unsigned long long* cand = g_cand + (long long)b * CAP;
    const float* lg = logits + (long long)b * N;

    __shared__ int hist[256];
    __shared__ unsigned long long sh_prefix;
    __shared__ int sh_remaining;
    if (tid == 0) { sh_prefix = 0ULL; sh_remaining = K; }
    __syncthreads();

    // MSD radix-select for the K-th largest 64-bit key (keys unique per element)
    for (int d = 7; d >= 0; --d) {
        hist[tid] = 0;                 // blockDim.x == 256
        __syncthreads();
        int shift = d * 8;
        unsigned long long pmask = (d == 7) ? 0ULL : (~0ULL << (shift + 8));
        unsigned long long prefix = sh_prefix;
        for (int i = tid; i < M; i += blockDim.x) {
            unsigned long long key = slow ? make_key(lg[i], (unsigned)i) : cand[i];
            if ((key & pmask) == prefix)
                atomicAdd(&hist[(int)((key >> shift) & 255)], 1);
        }
        __syncthreads();
        if (tid == 0) {
            int rem = sh_remaining;
            int cum = 0, chosen = 0;
            for (int bd = 255; bd >= 0; --bd) {
                cum += hist[bd];
                if (cum >= rem) {
                    chosen = bd;
                    sh_remaining = rem - (cum - hist[bd]);
                    break;
                }
            }
            sh_prefix = prefix | ((unsigned long long)chosen << shift);
        }
        __syncthreads();
    }
    unsigned long long kth = sh_prefix;   // exact K-th largest key

    // Collect winners: exactly K keys satisfy key >= kth (keys are unique)
    __shared__ unsigned long long win[KMAX];
    __shared__ int wc;
    if (tid == 0) wc = 0;
    __syncthreads();
    for (int i = tid; i < M; i += blockDim.x) {
        unsigned long long key = slow ? make_key(lg[i], (unsigned)i) : cand[i];
        if (key >= kth) {
            int p = atomicAdd(&wc, 1);
            if (p < KMAX) win[p] = key;
        }
    }
    __syncthreads();

    // Rank by pairwise comparison (K<=100, trivial), then emit outputs
    if (tid < K) {
        unsigned long long k0 = win[tid];
        int rank = 0;
        for (int j = 0; j < K; j++) rank += (win[j] > k0);
        float score = __uint_as_float((unsigned)(k0 >> 32));
        unsigned idx = ~(unsigned)(k0 & 0xffffffffu);
        int q = (int)(idx / (unsigned)C);
        int lbl = (int)(idx - (unsigned)q * (unsigned)C);
        float c = segs[((long long)b * Q + q) * 2 + 0];
        float w = segs[((long long)b * Q + q) * 2 + 1];
        float t = ts[b];
        int BK = B * K;
        int o = b * K + rank;
        out[o]                = score;
        out[BK + o]           = (float)lbl;
        out[2 * BK + 2 * o]     = (c - 0.5f * w) * t;
        out[2 * BK + 2 * o + 1] = (c + 0.5f * w) * t;
        out[4 * BK + o]       = (float)q;
    }
}

extern "C" void kernel_launch(void* const* d_in, const int* in_sizes, int n_in,
                              void* d_out, int out_size) {
    const float* logits = (const float*)d_in[0];   // [B, Q, C] f32
    const float* segs   = (const float*)d_in[1];   // [B, Q, 2] f32
    const float* ts     = (const float*)d_in[2];   // [B] f32

    int B = in_sizes[2];
    int N = in_sizes[0] / B;          // Q * C
    int Q = in_sizes[1] / (2 * B);
    int C = N / Q;
    int K = 100;
    if (K > N) K = N;

    k_zero<<<1, MAXB>>>(B);

    int per_cta = (((N + SLICES - 1) / SLICES) + 3) & ~3;
    dim3 gridA(SLICES, B);
    k_collect<<<gridA, TPB>>>(logits, N, 2.8f, per_cta);

    k_select<<<B, 256>>>(logits, segs, ts, (float*)d_out, B, Q, C, K);
}

// round 2
// speedup vs baseline: 1.3869x; 1.3869x over previous
#include <cuda_runtime.h>
#include <math.h>

// B=64 batches, per batch N=Q*C=400000 fp32 logits.
// Output f32 concat: scores[B*K] | labels[B*K] | segments[B*K*2] | query_ids[B*K].
//
// Single fused kernel:
//  - grid (SLICES, B): each CTA streams its slice of one batch's logits with
//    4-way batched float4 loads (MLP>=4), pushing rare candidates
//    (logit > 2.8, superset of top-100 for N(0,1) data with ~28-sigma margin)
//    as 64-bit keys (sigmoid_bits<<32)|~flat_idx into a per-batch buffer.
//  - last-arriving slice CTA per batch runs an exact MSD radix-select over the
//    ~1k L2-resident candidates, ranks the K winners, writes outputs, and
//    resets that batch's counters for the next graph replay.
//  - exact fallback: if candidate count is unusable, select runs directly over
//    the batch's N logits (never taken for this data, keeps kernel exact).

#define MAXB    64
#define CAP     16384
#define SLICES  16
#define TPB     256
#define KMAX    128

__device__ unsigned long long g_cand[MAXB * CAP];
__device__ int g_cnt[MAXB];
__device__ int g_done[MAXB];

__device__ __forceinline__ unsigned long long make_key(float x, unsigned idx) {
    float s = 1.0f / (1.0f + expf(-x));   // matches jax sigmoid ordering (verified rel_err 8e-9)
    return ((unsigned long long)__float_as_uint(s) << 32) | (unsigned long long)(~idx);
}

__device__ __forceinline__ void push4(float4 v, unsigned idx0, int b, float thresh) {
    #pragma unroll
    for (int j = 0; j < 4; j++) {
        float x = (j == 0) ? v.x : (j == 1) ? v.y : (j == 2) ? v.z : v.w;
        if (x > thresh) {
            int p = atomicAdd(&g_cnt[b], 1);
            if (p < CAP) g_cand[b * CAP + p] = make_key(x, idx0 + j);
        }
    }
}

__device__ __forceinline__ float max4(float4 v) {
    return fmaxf(fmaxf(v.x, v.y), fmaxf(v.z, v.w));
}

// ---- exact top-K selection over candidates (or full logits on fallback) ----
__device__ void do_select(const float* __restrict__ lg,
                          const float* __restrict__ segs,
                          const float* __restrict__ ts,
                          float* __restrict__ out,
                          int b, int B, int Q, int C, int K, int N) {
    int tid = threadIdx.x;
    int lane = tid & 31;
    int wid = tid >> 5;

    int cnt = g_cnt[b];
    bool slow = (cnt < K) || (cnt > CAP);
    int M = slow ? N : cnt;
    const unsigned long long* cand = g_cand + (long long)b * CAP;

    __shared__ int hist[256];
    __shared__ int wtot[8];
    __shared__ unsigned long long sh_prefix;
    __shared__ int sh_remaining;
    if (tid == 0) { sh_prefix = 0ULL; sh_remaining = K; }
    __syncthreads();

    for (int d = 7; d >= 0; --d) {
        hist[tid] = 0;
        __syncthreads();
        int shift = d * 8;
        unsigned long long pmask = (d == 7) ? 0ULL : (~0ULL << (shift + 8));
        unsigned long long prefix = sh_prefix;
        for (int i = tid; i < M; i += TPB) {
            unsigned long long key = slow ? make_key(lg[i], (unsigned)i) : cand[i];
            if ((key & pmask) == prefix)
                atomicAdd(&hist[(int)((key >> shift) & 255)], 1);
        }
        __syncthreads();
        int rem = sh_remaining;
        int h = hist[tid];
        // inclusive suffix-scan within warp (bins tid..warp_end)
        int x = h;
        #pragma unroll
        for (int off = 1; off < 32; off <<= 1) {
            int y = __shfl_down_sync(0xffffffffu, x, off);
            if (lane + off < 32) x += y;
        }
        if (lane == 0) wtot[wid] = x;   // warp segment total = suffix at its first bin
        __syncthreads();
        int wsum = 0;
        #pragma unroll
        for (int w = 0; w < 8; w++) if (w > wid) wsum += wtot[w];
        int suffix = x + wsum;          // sum of hist[tid..255]
        // unique chosen bin: suffix >= rem && suffix - h < rem
        if (suffix >= rem && (suffix - h) < rem) {
            sh_prefix = prefix | ((unsigned long long)tid << shift);
            sh_remaining = rem - (suffix - h);
        }
        __syncthreads();
    }
    unsigned long long kth = sh_prefix;   // exact K-th largest key (keys unique)

    __shared__ unsigned long long win[KMAX];
    __shared__ int wc;
    if (tid == 0) wc = 0;
    __syncthreads();
    for (int i = tid; i < M; i += TPB) {
        unsigned long long key = slow ? make_key(lg[i], (unsigned)i) : cand[i];
        if (key >= kth) {
            int p = atomicAdd(&wc, 1);
            if (p < KMAX) win[p] = key;
        }
    }
    __syncthreads();

    if (tid < K) {
        unsigned long long k0 = win[tid];
        int rank = 0;
        for (int j = 0; j < K; j++) rank += (win[j] > k0);
        float score = __uint_as_float((unsigned)(k0 >> 32));
        unsigned idx = ~(unsigned)(k0 & 0xffffffffu);
        int q = (int)(idx / (unsigned)C);
        int lbl = (int)(idx - (unsigned)q * (unsigned)C);
        float c = segs[((long long)b * Q + q) * 2 + 0];
        float w = segs[((long long)b * Q + q) * 2 + 1];
        float t = ts[b];
        int BK = B * K;
        int o = b * K + rank;
        out[o]                  = score;
        out[BK + o]             = (float)lbl;
        out[2 * BK + 2 * o]     = (c - 0.5f * w) * t;
        out[2 * BK + 2 * o + 1] = (c + 0.5f * w) * t;
        out[4 * BK + o]         = (float)q;
    }
    __syncthreads();
    if (tid == 0) { g_done[b] = 0; g_cnt[b] = 0; }   // reset for next graph replay
}

__global__ void __launch_bounds__(TPB, 8)
k_main(const float* __restrict__ logits,
       const float* __restrict__ segs,
       const float* __restrict__ ts,
       float* __restrict__ out,
       int B, int Q, int C, int K, int per_cta, float thresh) {
    int b = blockIdx.y;
    int N = Q * C;
    int start = blockIdx.x * per_cta;
    int tid = threadIdx.x;

    if (start < N) {
        int count = min(per_cta, N - start);
        const float* base = logits + (long long)b * N + start;
        const float4* p4 = (const float4*)base;    // start is a multiple of 4 elems
        int n4 = count >> 2;

        int i = tid;
        // main loop: 4 independent float4 loads per iteration (MLP >= 4)
        for (; i + 3 * TPB < n4; i += 4 * TPB) {
            float4 a0 = p4[i];
            float4 a1 = p4[i + TPB];
            float4 a2 = p4[i + 2 * TPB];
            float4 a3 = p4[i + 3 * TPB];
            float m = fmaxf(fmaxf(max4(a0), max4(a1)), fmaxf(max4(a2), max4(a3)));
            if (m > thresh) {
                push4(a0, (unsigned)(start + 4 * i), b, thresh);
                push4(a1, (unsigned)(start + 4 * (i + TPB)), b, thresh);
                push4(a2, (unsigned)(start + 4 * (i + 2 * TPB)), b, thresh);
                push4(a3, (unsigned)(start + 4 * (i + 3 * TPB)), b, thresh);
            }
        }
        for (; i < n4; i += TPB) {
            float4 a0 = p4[i];
            if (max4(a0) > thresh)
                push4(a0, (unsigned)(start + 4 * i), b, thresh);
        }
        // scalar tail (only if count % 4 != 0)
        int tail = count & 3;
        if (tail && tid == 0) {
            for (int t = 0; t < tail; t++) {
                float x = base[(n4 << 2) + t];
                if (x > thresh) {
                    int p = atomicAdd(&g_cnt[b], 1);
                    if (p < CAP)
                        g_cand[b * CAP + p] = make_key(x, (unsigned)(start + (n4 << 2) + t));
                }
            }
        }
    }

    // ---- arrival: last slice CTA of this batch performs the selection ----
    __threadfence();
    __syncthreads();
    __shared__ int is_last;
    if (tid == 0)
        is_last = (atomicAdd(&g_done[b], 1) == gridDim.x - 1);
    __syncthreads();
    if (is_last) {
        __threadfence();   // acquire: make other CTAs' candidate stores visible
        do_select(logits + (long long)b * N, segs, ts, out, b, B, Q, C, K, N);
    }
}

extern "C" void kernel_launch(void* const* d_in, const int* in_sizes, int n_in,
                              void* d_out, int out_size) {
    const float* logits = (const float*)d_in[0];   // [B, Q, C] f32
    const float* segs   = (const float*)d_in[1];   // [B, Q, 2] f32
    const float* ts     = (const float*)d_in[2];   // [B] f32

    int B = in_sizes[2];
    int N = in_sizes[0] / B;          // Q * C
    int Q = in_sizes[1] / (2 * B);
    int C = N / Q;
    int K = 100;
    if (K > N) K = N;

    int per_cta = (((N + SLICES - 1) / SLICES) + 3) & ~3;
    dim3 grid(SLICES, B);
    k_main<<<grid, TPB>>>(logits, segs, ts, (float*)d_out, B, Q, C, K, per_cta, 2.8f);
}

// round 3
// speedup vs baseline: 2.0577x; 1.4837x over previous
#include <cuda_runtime.h>
#include <math.h>

// B=64 batches, per batch N=Q*C=400000 fp32 logits.
// Output f32 concat: scores[B*K] | labels[B*K] | segments[B*K*2] | query_ids[B*K].
//
// Single fused kernel, grid (SLICES, B):
//  - collect: 8-way batched float4 streaming (high MLP), hits (logit > 2.8,
//    superset of top-100 for N(0,1) with ~28-sigma margin) staged in smem,
//    bulk-flushed to a per-batch global candidate buffer.
//  - last-arriving slice CTA per batch: exact MSD radix-select over the ~1k
//    L2-resident candidates, rank K winners, emit outputs, reset counters.
//  - exact fallback over the full batch if the candidate set is unusable.

#define MAXB    64
#define CAP     16384
#define SLICES  16
#define TPB     256
#define KMAX    128
#define SBUF    768

__device__ unsigned long long g_cand[MAXB * CAP];
__device__ int g_cnt[MAXB];
__device__ int g_done[MAXB];

__device__ __forceinline__ unsigned long long make_key(float x, unsigned idx) {
    float s = 1.0f / (1.0f + expf(-x));   // sigmoid ordering == jax (rel_err 8e-9 verified)
    return ((unsigned long long)__float_as_uint(s) << 32) | (unsigned long long)(~idx);
}

__device__ __forceinline__ float max4(float4 v) {
    return fmaxf(fmaxf(v.x, v.y), fmaxf(v.z, v.w));
}

// ---- exact top-K selection over candidates (or full logits on fallback) ----
__device__ void do_select(const float* __restrict__ lg,
                          const float* __restrict__ segs,
                          const float* __restrict__ ts,
                          float* __restrict__ out,
                          int b, int B, int Q, int C, int K, int N) {
    int tid = threadIdx.x;
    int lane = tid & 31;
    int wid = tid >> 5;

    int cnt = g_cnt[b];
    bool slow = (cnt < K) || (cnt > CAP);
    int M = slow ? N : cnt;
    const unsigned long long* cand = g_cand + (long long)b * CAP;

    __shared__ int hist[256];
    __shared__ int wtot[8];
    __shared__ unsigned long long sh_prefix;
    __shared__ int sh_remaining;
    if (tid == 0) { sh_prefix = 0ULL; sh_remaining = K; }
    __syncthreads();

    for (int d = 7; d >= 0; --d) {
        hist[tid] = 0;
        __syncthreads();
        int shift = d * 8;
        unsigned long long pmask = (d == 7) ? 0ULL : (~0ULL << (shift + 8));
        unsigned long long prefix = sh_prefix;
        for (int i = tid; i < M; i += TPB) {
            unsigned long long key = slow ? make_key(lg[i], (unsigned)i) : cand[i];
            if ((key & pmask) == prefix)
                atomicAdd(&hist[(int)((key >> shift) & 255)], 1);
        }
        __syncthreads();
        int rem = sh_remaining;
        int h = hist[tid];
        int x = h;                      // suffix-scan within warp
        #pragma unroll
        for (int off = 1; off < 32; off <<= 1) {
            int y = __shfl_down_sync(0xffffffffu, x, off);
            if (lane + off < 32) x += y;
        }
        if (lane == 0) wtot[wid] = x;
        __syncthreads();
        int wsum = 0;
        #pragma unroll
        for (int w = 0; w < 8; w++) if (w > wid) wsum += wtot[w];
        int suffix = x + wsum;          // sum of hist[tid..255]
        if (suffix >= rem && (suffix - h) < rem) {   // unique chosen bin
            sh_prefix = prefix | ((unsigned long long)tid << shift);
            sh_remaining = rem - (suffix - h);
        }
        __syncthreads();
    }
    unsigned long long kth = sh_prefix;   // exact K-th largest key (keys unique)

    __shared__ unsigned long long win[KMAX];
    __shared__ int wc;
    if (tid == 0) wc = 0;
    __syncthreads();
    for (int i = tid; i < M; i += TPB) {
        unsigned long long key = slow ? make_key(lg[i], (unsigned)i) : cand[i];
        if (key >= kth) {
            int p = atomicAdd(&wc, 1);
            if (p < KMAX) win[p] = key;
        }
    }
    __syncthreads();

    if (tid < K) {
        unsigned long long k0 = win[tid];
        int rank = 0;
        for (int j = 0; j < K; j++) rank += (win[j] > k0);
        float score = __uint_as_float((unsigned)(k0 >> 32));
        unsigned idx = ~(unsigned)(k0 & 0xffffffffu);
        int q = (int)(idx / (unsigned)C);
        int lbl = (int)(idx - (unsigned)q * (unsigned)C);
        float c = segs[((long long)b * Q + q) * 2 + 0];
        float w = segs[((long long)b * Q + q) * 2 + 1];
        float t = ts[b];
        int BK = B * K;
        int o = b * K + rank;
        out[o]                  = score;
        out[BK + o]             = (float)lbl;
        out[2 * BK + 2 * o]     = (c - 0.5f * w) * t;
        out[2 * BK + 2 * o + 1] = (c + 0.5f * w) * t;
        out[4 * BK + o]         = (float)q;
    }
    __syncthreads();
    if (tid == 0) { g_done[b] = 0; g_cnt[b] = 0; }   // reset for next graph replay
}

__global__ void __launch_bounds__(TPB, 4)
k_main(const float* __restrict__ logits,
       const float* __restrict__ segs,
       const float* __restrict__ ts,
       float* __restrict__ out,
       int B, int Q, int C, int K, int per_cta, float thresh) {
    int b = blockIdx.y;
    int N = Q * C;
    int start = blockIdx.x * per_cta;
    int tid = threadIdx.x;

    __shared__ unsigned long long s_buf[SBUF];
    __shared__ int s_cnt;
    __shared__ int s_base;
    if (tid == 0) s_cnt = 0;
    __syncthreads();

    auto push_hit = [&](float x, unsigned idx) {
        int pos = atomicAdd(&s_cnt, 1);
        if (pos < SBUF) {
            s_buf[pos] = make_key(x, idx);
        } else {                                   // smem overflow: direct global (rare)
            int p = atomicAdd(&g_cnt[b], 1);
            if (p < CAP) g_cand[b * CAP + p] = make_key(x, idx);
        }
    };
    auto check4 = [&](float4 v, unsigned idx0) {
        if (v.x > thresh) push_hit(v.x, idx0);
        if (v.y > thresh) push_hit(v.y, idx0 + 1);
        if (v.z > thresh) push_hit(v.z, idx0 + 2);
        if (v.w > thresh) push_hit(v.w, idx0 + 3);
    };

    if (start < N) {
        int count = min(per_cta, N - start);
        const float* base = logits + (long long)b * N + start;
        const float4* p4 = (const float4*)base;    // start is a multiple of 4 elems
        int n4 = count >> 2;

        int i = tid;
        // 8 independent float4 loads per iteration (MLP >= 8)
        for (; i + 7 * TPB < n4; i += 8 * TPB) {
            float4 a0 = p4[i];
            float4 a1 = p4[i + TPB];
            float4 a2 = p4[i + 2 * TPB];
            float4 a3 = p4[i + 3 * TPB];
            float4 a4 = p4[i + 4 * TPB];
            float4 a5 = p4[i + 5 * TPB];
            float4 a6 = p4[i + 6 * TPB];
            float4 a7 = p4[i + 7 * TPB];
            float m = fmaxf(fmaxf(fmaxf(max4(a0), max4(a1)), fmaxf(max4(a2), max4(a3))),
                            fmaxf(fmaxf(max4(a4), max4(a5)), fmaxf(max4(a6), max4(a7))));
            if (m > thresh) {
                check4(a0, (unsigned)(start + 4 * i));
                check4(a1, (unsigned)(start + 4 * (i + TPB)));
                check4(a2, (unsigned)(start + 4 * (i + 2 * TPB)));
                check4(a3, (unsigned)(start + 4 * (i + 3 * TPB)));
                check4(a4, (unsigned)(start + 4 * (i + 4 * TPB)));
                check4(a5, (unsigned)(start + 4 * (i + 5 * TPB)));
                check4(a6, (unsigned)(start + 4 * (i + 6 * TPB)));
                check4(a7, (unsigned)(start + 4 * (i + 7 * TPB)));
            }
        }
        // 4-way remainder
        for (; i + 3 * TPB < n4; i += 4 * TPB) {
            float4 a0 = p4[i];
            float4 a1 = p4[i + TPB];
            float4 a2 = p4[i + 2 * TPB];
            float4 a3 = p4[i + 3 * TPB];
            float m = fmaxf(fmaxf(max4(a0), max4(a1)), fmaxf(max4(a2), max4(a3)));
            if (m > thresh) {
                check4(a0, (unsigned)(start + 4 * i));
                check4(a1, (unsigned)(start + 4 * (i + TPB)));
                check4(a2, (unsigned)(start + 4 * (i + 2 * TPB)));
                check4(a3, (unsigned)(start + 4 * (i + 3 * TPB)));
            }
        }
        // singles
        for (; i < n4; i += TPB) {
            float4 a0 = p4[i];
            if (max4(a0) > thresh) check4(a0, (unsigned)(start + 4 * i));
        }
        // scalar tail (only if count % 4 != 0)
        int tail = count & 3;
        if (tail && tid == 0) {
            for (int t = 0; t < tail; t++) {
                float x = base[(n4 << 2) + t];
                if (x > thresh) push_hit(x, (unsigned)(start + (n4 << 2) + t));
            }
        }
    }

    // ---- flush smem candidates to global ----
    __syncthreads();
    int cnt = min(s_cnt, SBUF);
    if (tid == 0) s_base = atomicAdd(&g_cnt[b], cnt);
    __syncthreads();
    int bs = s_base;
    for (int i2 = tid; i2 < cnt; i2 += TPB) {
        int p = bs + i2;
        if (p < CAP) g_cand[b * CAP + p] = s_buf[i2];
    }

    // ---- arrival: last slice CTA of this batch performs the selection ----
    __threadfence();
    __syncthreads();
    __shared__ int is_last;
    if (tid == 0)
        is_last = (atomicAdd(&g_done[b], 1) == gridDim.x - 1);
    __syncthreads();
    if (is_last) {
        __threadfence();   // acquire: other CTAs' candidate stores visible
        do_select(logits + (long long)b * N, segs, ts, out, b, B, Q, C, K, N);
    }
}

extern "C" void kernel_launch(void* const* d_in, const int* in_sizes, int n_in,
                              void* d_out, int out_size) {
    const float* logits = (const float*)d_in[0];   // [B, Q, C] f32
    const float* segs   = (const float*)d_in[1];   // [B, Q, 2] f32
    const float* ts     = (const float*)d_in[2];   // [B] f32

    int B = in_sizes[2];
    int N = in_sizes[0] / B;          // Q * C
    int Q = in_sizes[1] / (2 * B);
    int C = N / Q;
    int K = 100;
    if (K > N) K = N;

    int per_cta = (((N + SLICES - 1) / SLICES) + 3) & ~3;
    dim3 grid(SLICES, B);
    k_main<<<grid, TPB>>>(logits, segs, ts, (float*)d_out, B, Q, C, K, per_cta, 2.8f);
}

// round 4
// speedup vs baseline: 2.2537x; 1.0952x over previous
#include <cuda_runtime.h>
#include <math.h>
#include <stdint.h>

// B=64 batches, per batch N=Q*C=400000 fp32 logits.
// Output f32 concat: scores[B*K] | labels[B*K] | segments[B*K*2] | query_ids[B*K].
//
// Single fused kernel, grid (SLICES, B) = (8, 64) = 512 CTAs (one wave):
//  - collect: TMA (cp.async.bulk) 4-stage pipeline streams 8KB tiles into smem;
//    threads scan tiles from smem, staging rare hits (logit > 2.8, a superset
//    of top-100 for N(0,1) data with ~28-sigma margin) in a smem buffer,
//    bulk-flushed to a per-batch global candidate buffer.
//  - last-arriving slice CTA per batch: exact MSD radix-select over the ~1k
//    candidates (cached in the now-free tile smem), rank K winners, emit
//    outputs, reset counters for the next graph replay.
//  - exact fallback over the full batch if the candidate set is unusable.

#define MAXB    64
#define CAP     16384
#define SLICES  8
#define TPB     256
#define KMAX    128
#define SBUF    384
#define NBUF    4
#define TILE_F  2048              // floats per tile (8 KB)
#define SELCACHE (NBUF * TILE_F / 2)   // 4096 u64 slots in tile smem

__device__ unsigned long long g_cand[MAXB * CAP];
__device__ int g_cnt[MAXB];
__device__ int g_done[MAXB];

__device__ __forceinline__ unsigned long long make_key(float x, unsigned idx) {
    float s = 1.0f / (1.0f + expf(-x));   // sigmoid ordering == jax (rel_err 8e-9 verified)
    return ((unsigned long long)__float_as_uint(s) << 32) | (unsigned long long)(~idx);
}

__device__ __forceinline__ float max4(float4 v) {
    return fmaxf(fmaxf(v.x, v.y), fmaxf(v.z, v.w));
}

__device__ __forceinline__ uint32_t smem_u32(const void* p) {
    uint32_t a;
    asm("{ .reg .u64 t; cvta.to.shared.u64 t, %1; cvt.u32.u64 %0, t; }" : "=r"(a) : "l"(p));
    return a;
}

__device__ __forceinline__ void mbar_init(uint32_t mbar, uint32_t count) {
    asm volatile("mbarrier.init.shared.b64 [%0], %1;" :: "r"(mbar), "r"(count) : "memory");
}

__device__ __forceinline__ void mbar_wait(uint32_t mbar, uint32_t parity) {
    asm volatile(
        "{\n\t.reg .pred P;\n"
        "W_%=:\n\t"
        "mbarrier.try_wait.parity.acquire.cta.shared::cta.b64 P, [%0], %1, 0x989680;\n\t"
        "@!P bra W_%=;\n\t}"
        :: "r"(mbar), "r"(parity) : "memory");
}

__device__ __forceinline__ void tma_issue(uint32_t dst, const float* src, uint32_t bytes,
                                          uint32_t mbar) {
    asm volatile("mbarrier.arrive.expect_tx.shared.b64 _, [%0], %1;"
                 :: "r"(mbar), "r"(bytes) : "memory");
    asm volatile("cp.async.bulk.shared::cluster.global.mbarrier::complete_tx::bytes "
                 "[%0], [%1], %2, [%3];"
                 :: "r"(dst), "l"(src), "r"(bytes), "r"(mbar) : "memory");
}

// ---- exact top-K selection over candidates (or full logits on fallback) ----
__device__ void do_select(const float* __restrict__ lg,
                          const float* __restrict__ segs,
                          const float* __restrict__ ts,
                          float* __restrict__ out,
                          unsigned long long* s_cache,
                          int b, int B, int Q, int C, int K, int N) {
    int tid = threadIdx.x;
    int lane = tid & 31;
    int wid = tid >> 5;

    int cnt = g_cnt[b];
    bool slow = (cnt < K) || (cnt > CAP);
    int M = slow ? N : cnt;
    const unsigned long long* cand = g_cand + (long long)b * CAP;

    // cache candidates in smem (tile buffers are free now)
    bool cached = (!slow) && (M <= SELCACHE);
    if (cached) {
        for (int i = tid; i < M; i += TPB) s_cache[i] = cand[i];
    }
    __shared__ int hist[256];
    __shared__ int wtot[8];
    __shared__ unsigned long long sh_prefix;
    __shared__ int sh_remaining;
    if (tid == 0) { sh_prefix = 0ULL; sh_remaining = K; }
    __syncthreads();

    for (int d = 7; d >= 0; --d) {
        hist[tid] = 0;
        __syncthreads();
        int shift = d * 8;
        unsigned long long pmask = (d == 7) ? 0ULL : (~0ULL << (shift + 8));
        unsigned long long prefix = sh_prefix;
        for (int i = tid; i < M; i += TPB) {
            unsigned long long key = cached ? s_cache[i]
                                   : (slow ? make_key(lg[i], (unsigned)i) : cand[i]);
            if ((key & pmask) == prefix)
                atomicAdd(&hist[(int)((key >> shift) & 255)], 1);
        }
        __syncthreads();
        int rem = sh_remaining;
        int h = hist[tid];
        int x = h;                      // suffix-scan within warp
        #pragma unroll
        for (int off = 1; off < 32; off <<= 1) {
            int y = __shfl_down_sync(0xffffffffu, x, off);
            if (lane + off < 32) x += y;
        }
        if (lane == 0) wtot[wid] = x;
        __syncthreads();
        int wsum = 0;
        #pragma unroll
        for (int w = 0; w < 8; w++) if (w > wid) wsum += wtot[w];
        int suffix = x + wsum;          // sum of hist[tid..255]
        if (suffix >= rem && (suffix - h) < rem) {   // unique chosen bin
            sh_prefix = prefix | ((unsigned long long)tid << shift);
            sh_remaining = rem - (suffix - h);
        }
        __syncthreads();
    }
    unsigned long long kth = sh_prefix;   // exact K-th largest key (keys unique)

    __shared__ unsigned long long win[KMAX];
    __shared__ int wc;
    if (tid == 0) wc = 0;
    __syncthreads();
    for (int i = tid; i < M; i += TPB) {
        unsigned long long key = cached ? s_cache[i]
                               : (slow ? make_key(lg[i], (unsigned)i) : cand[i]);
        if (key >= kth) {
            int p = atomicAdd(&wc, 1);
            if (p < KMAX) win[p] = key;
        }
    }
    __syncthreads();

    if (tid < K) {
        unsigned long long k0 = win[tid];
        int rank = 0;
        for (int j = 0; j < K; j++) rank += (win[j] > k0);
        float score = __uint_as_float((unsigned)(k0 >> 32));
        unsigned idx = ~(unsigned)(k0 & 0xffffffffu);
        int q = (int)(idx / (unsigned)C);
        int lbl = (int)(idx - (unsigned)q * (unsigned)C);
        float c = segs[((long long)b * Q + q) * 2 + 0];
        float w = segs[((long long)b * Q + q) * 2 + 1];
        float t = ts[b];
        int BK = B * K;
        int o = b * K + rank;
        out[o]                  = score;
        out[BK + o]             = (float)lbl;
        out[2 * BK + 2 * o]     = (c - 0.5f * w) * t;
        out[2 * BK + 2 * o + 1] = (c + 0.5f * w) * t;
        out[4 * BK + o]         = (float)q;
    }
    __syncthreads();
    if (tid == 0) { g_done[b] = 0; g_cnt[b] = 0; }   // reset for next graph replay
}

__global__ void __launch_bounds__(TPB)
k_main(const float* __restrict__ logits,
       const float* __restrict__ segs,
       const float* __restrict__ ts,
       float* __restrict__ out,
       int B, int Q, int C, int K, int per_cta, float thresh) {
    int b = blockIdx.y;
    int N = Q * C;
    int start = blockIdx.x * per_cta;
    int tid = threadIdx.x;

    __shared__ __align__(128) float4 s_tile[NBUF][TILE_F / 4];   // 32 KB
    __shared__ __align__(8) unsigned long long s_mbar[NBUF];
    __shared__ unsigned long long s_buf[SBUF];
    __shared__ int s_cnt;
    __shared__ int s_base;

    if (tid == 0) s_cnt = 0;
    if (tid < NBUF) mbar_init(smem_u32(&s_mbar[tid]), 1);
    __syncthreads();

    auto push_hit = [&](float x, unsigned idx) {
        int pos = atomicAdd(&s_cnt, 1);
        if (pos < SBUF) {
            s_buf[pos] = make_key(x, idx);
        } else {                                   // smem overflow: direct global (rare)
            int p = atomicAdd(&g_cnt[b], 1);
            if (p < CAP) g_cand[b * CAP + p] = make_key(x, idx);
        }
    };

    if (start < N) {
        int count = min(per_cta, N - start);
        const float* base = logits + (long long)b * N + start;
        int cnt4 = count & ~3;                      // TMA bytes must be %16
        int tiles = (cnt4 + TILE_F - 1) / TILE_F;

        // prologue: fill pipeline with up to NBUF-1 copies
        if (tid == 0) {
            for (int t = 0; t < tiles && t < NBUF - 1; t++) {
                int te = min(TILE_F, cnt4 - t * TILE_F);
                tma_issue(smem_u32(&s_tile[t & (NBUF - 1)][0]), base + t * TILE_F,
                          (uint32_t)(te * 4), smem_u32(&s_mbar[t & (NBUF - 1)]));
            }
        }

        for (int t = 0; t < tiles; t++) {
            int s = t & (NBUF - 1);
            mbar_wait(smem_u32(&s_mbar[s]), (uint32_t)((t >> 2) & 1));
            // keep pipeline full: buffer (t+3)&3 was consumed at iteration t-1
            if (tid == 0 && t + NBUF - 1 < tiles) {
                int tn = t + NBUF - 1;
                int te = min(TILE_F, cnt4 - tn * TILE_F);
                tma_issue(smem_u32(&s_tile[tn & (NBUF - 1)][0]), base + tn * TILE_F,
                          (uint32_t)(te * 4), smem_u32(&s_mbar[tn & (NBUF - 1)]));
            }
            int te = min(TILE_F, cnt4 - t * TILE_F);
            int nf4 = te >> 2;
            unsigned gbase = (unsigned)(start + t * TILE_F);
            for (int j = tid; j < nf4; j += TPB) {
                float4 v = s_tile[s][j];
                if (max4(v) > thresh) {
                    unsigned i0 = gbase + 4 * j;
                    if (v.x > thresh) push_hit(v.x, i0);
                    if (v.y > thresh) push_hit(v.y, i0 + 1);
                    if (v.z > thresh) push_hit(v.z, i0 + 2);
                    if (v.w > thresh) push_hit(v.w, i0 + 3);
                }
            }
            __syncthreads();
        }
        // scalar tail (only if count % 4 != 0; never for this shape)
        int tail = count - cnt4;
        if (tid < tail) {
            float x = base[cnt4 + tid];
            if (x > thresh) push_hit(x, (unsigned)(start + cnt4 + tid));
        }
    }

    // ---- flush smem candidates to global ----
    __syncthreads();
    int cnt = min(s_cnt, SBUF);
    if (tid == 0) s_base = atomicAdd(&g_cnt[b], cnt);
    __syncthreads();
    int bs = s_base;
    for (int i2 = tid; i2 < cnt; i2 += TPB) {
        int p = bs + i2;
        if (p < CAP) g_cand[b * CAP + p] = s_buf[i2];
    }

    // ---- arrival: last slice CTA of this batch performs the selection ----
    __threadfence();
    __syncthreads();
    __shared__ int is_last;
    if (tid == 0)
        is_last = (atomicAdd(&g_done[b], 1) == gridDim.x - 1);
    __syncthreads();
    if (is_last) {
        __threadfence();   // acquire: other CTAs' candidate stores visible
        do_select(logits + (long long)b * N, segs, ts, out,
                  (unsigned long long*)&s_tile[0][0], b, B, Q, C, K, N);
    }
}

extern "C" void kernel_launch(void* const* d_in, const int* in_sizes, int n_in,
                              void* d_out, int out_size) {
    const float* logits = (const float*)d_in[0];   // [B, Q, C] f32
    const float* segs   = (const float*)d_in[1];   // [B, Q, 2] f32
    const float* ts     = (const float*)d_in[2];   // [B] f32

    int B = in_sizes[2];
    int N = in_sizes[0] / B;          // Q * C
    int Q = in_sizes[1] / (2 * B);
    int C = N / Q;
    int K = 100;
    if (K > N) K = N;

    int per_cta = (((N + SLICES - 1) / SLICES) + 3) & ~3;
    dim3 grid(SLICES, B);
    k_main<<<grid, TPB>>>(logits, segs, ts, (float*)d_out, B, Q, C, K, per_cta, 2.8f);
}

// round 5
// speedup vs baseline: 2.7387x; 1.2152x over previous
#include <cuda_runtime.h>
#include <math.h>
#include <stdint.h>

// B=64 batches, per batch N=Q*C=400000 fp32 logits.
// Output f32 concat: scores[B*K] | labels[B*K] | segments[B*K*2] | query_ids[B*K].
//
// Single fused kernel, grid (SLICES, B) = (8, 64) = 512 CTAs (one wave):
//  - collect: per-thread cp.async (LDGSTS) ring, DEPTH=8 x 16B slots per thread.
//    Hardware async queues give guaranteed MLP=8/thread with no block-level
//    synchronization in the hot loop. Hits (logit > 2.8, superset of top-100
//    for N(0,1) data with ~28-sigma margin) staged in smem, bulk-flushed to a
//    per-batch global candidate buffer.
//  - last-arriving slice CTA per batch: exact MSD radix-select over the ~1k
//    candidates (cached in the now-free pipe smem), rank K winners, emit
//    outputs, reset counters for the next graph replay.
//  - exact fallback over the full batch if the candidate set is unusable.

#define MAXB    64
#define CAP     16384
#define SLICES  8
#define TPB     256
#define KMAX    128
#define SBUF    384
#define DEPTH   8
#define SELCACHE 4096     // u64 slots available in pipe smem (32KB)

__device__ unsigned long long g_cand[MAXB * CAP];
__device__ int g_cnt[MAXB];
__device__ int g_done[MAXB];

__device__ __forceinline__ unsigned long long make_key(float x, unsigned idx) {
    float s = 1.0f / (1.0f + expf(-x));   // sigmoid ordering == jax (rel_err 8e-9 verified)
    return ((unsigned long long)__float_as_uint(s) << 32) | (unsigned long long)(~idx);
}

__device__ __forceinline__ float max4(float4 v) {
    return fmaxf(fmaxf(v.x, v.y), fmaxf(v.z, v.w));
}

__device__ __forceinline__ uint32_t smem_u32(const void* p) {
    uint32_t a;
    asm("{ .reg .u64 t; cvta.to.shared.u64 t, %1; cvt.u32.u64 %0, t; }" : "=r"(a) : "l"(p));
    return a;
}

__device__ __forceinline__ void cp_async16(uint32_t dst, const float4* src) {
    asm volatile("cp.async.cg.shared.global [%0], [%1], 16;"
                 :: "r"(dst), "l"(src) : "memory");
}
__device__ __forceinline__ void cp_commit() {
    asm volatile("cp.async.commit_group;" ::: "memory");
}
__device__ __forceinline__ void cp_wait_most() {       // allow DEPTH-1 outstanding
    asm volatile("cp.async.wait_group %0;" :: "n"(DEPTH - 1) : "memory");
}
__device__ __forceinline__ void cp_wait_all() {
    asm volatile("cp.async.wait_all;" ::: "memory");
}

// ---- exact top-K selection over candidates (or full logits on fallback) ----
__device__ void do_select(const float* __restrict__ lg,
                          const float* __restrict__ segs,
                          const float* __restrict__ ts,
                          float* __restrict__ out,
                          unsigned long long* s_cache,
                          int b, int B, int Q, int C, int K, int N) {
    int tid = threadIdx.x;
    int lane = tid & 31;
    int wid = tid >> 5;

    int cnt = g_cnt[b];
    bool slow = (cnt < K) || (cnt > CAP);
    int M = slow ? N : cnt;
    const unsigned long long* cand = g_cand + (long long)b * CAP;

    bool cached = (!slow) && (M <= SELCACHE);   // pipe smem is free now
    if (cached) {
        for (int i = tid; i < M; i += TPB) s_cache[i] = cand[i];
    }
    __shared__ int hist[256];
    __shared__ int wtot[8];
    __shared__ unsigned long long sh_prefix;
    __shared__ int sh_remaining;
    if (tid == 0) { sh_prefix = 0ULL; sh_remaining = K; }
    __syncthreads();

    for (int d = 7; d >= 0; --d) {
        hist[tid] = 0;
        __syncthreads();
        int shift = d * 8;
        unsigned long long pmask = (d == 7) ? 0ULL : (~0ULL << (shift + 8));
        unsigned long long prefix = sh_prefix;
        for (int i = tid; i < M; i += TPB) {
            unsigned long long key = cached ? s_cache[i]
                                   : (slow ? make_key(lg[i], (unsigned)i) : cand[i]);
            if ((key & pmask) == prefix)
                atomicAdd(&hist[(int)((key >> shift) & 255)], 1);
        }
        __syncthreads();
        int rem = sh_remaining;
        int h = hist[tid];
        int x = h;                      // suffix-scan within warp
        #pragma unroll
        for (int off = 1; off < 32; off <<= 1) {
            int y = __shfl_down_sync(0xffffffffu, x, off);
            if (lane + off < 32) x += y;
        }
        if (lane == 0) wtot[wid] = x;
        __syncthreads();
        int wsum = 0;
        #pragma unroll
        for (int w = 0; w < 8; w++) if (w > wid) wsum += wtot[w];
        int suffix = x + wsum;          // sum of hist[tid..255]
        if (suffix >= rem && (suffix - h) < rem) {   // unique chosen bin
            sh_prefix = prefix | ((unsigned long long)tid << shift);
            sh_remaining = rem - (suffix - h);
        }
        __syncthreads();
    }
    unsigned long long kth = sh_prefix;   // exact K-th largest key (keys unique)

    __shared__ unsigned long long win[KMAX];
    __shared__ int wc;
    if (tid == 0) wc = 0;
    __syncthreads();
    for (int i = tid; i < M; i += TPB) {
        unsigned long long key = cached ? s_cache[i]
                               : (slow ? make_key(lg[i], (unsigned)i) : cand[i]);
        if (key >= kth) {
            int p = atomicAdd(&wc, 1);
            if (p < KMAX) win[p] = key;
        }
    }
    __syncthreads();

    if (tid < K) {
        unsigned long long k0 = win[tid];
        int rank = 0;
        for (int j = 0; j < K; j++) rank += (win[j] > k0);
        float score = __uint_as_float((unsigned)(k0 >> 32));
        unsigned idx = ~(unsigned)(k0 & 0xffffffffu);
        int q = (int)(idx / (unsigned)C);
        int lbl = (int)(idx - (unsigned)q * (unsigned)C);
        float c = segs[((long long)b * Q + q) * 2 + 0];
        float w = segs[((long long)b * Q + q) * 2 + 1];
        float t = ts[b];
        int BK = B * K;
        int o = b * K + rank;
        out[o]                  = score;
        out[BK + o]             = (float)lbl;
        out[2 * BK + 2 * o]     = (c - 0.5f * w) * t;
        out[2 * BK + 2 * o + 1] = (c + 0.5f * w) * t;
        out[4 * BK + o]         = (float)q;
    }
    __syncthreads();
    if (tid == 0) { g_done[b] = 0; g_cnt[b] = 0; }   // reset for next graph replay
}

__global__ void __launch_bounds__(TPB)
k_main(const float* __restrict__ logits,
       const float* __restrict__ segs,
       const float* __restrict__ ts,
       float* __restrict__ out,
       int B, int Q, int C, int K, int per_cta, float thresh) {
    int b = blockIdx.y;
    int N = Q * C;
    int start = blockIdx.x * per_cta;
    int tid = threadIdx.x;

    __shared__ __align__(16) float4 s_pipe[DEPTH][TPB];   // 32 KB, per-thread columns
    __shared__ unsigned long long s_buf[SBUF];
    __shared__ int s_cnt;
    __shared__ int s_base;

    if (tid == 0) s_cnt = 0;
    __syncthreads();

    auto push_hit = [&](float x, unsigned idx) {
        int pos = atomicAdd(&s_cnt, 1);
        if (pos < SBUF) {
            s_buf[pos] = make_key(x, idx);
        } else {                                   // smem overflow: direct global (rare)
            int p = atomicAdd(&g_cnt[b], 1);
            if (p < CAP) g_cand[b * CAP + p] = make_key(x, idx);
        }
    };

    if (start < N) {
        int count = min(per_cta, N - start);
        const float* base = logits + (long long)b * N + start;
        const float4* src = (const float4*)base;   // start is a multiple of 4 floats
        int n4 = count >> 2;
        int iters = (n4 + TPB - 1) / TPB;
        uint32_t myslot0 = smem_u32(&s_pipe[0][tid]);

        // prologue: fill per-thread ring (one commit group per slot, always commit
        // so group numbering stays uniform; empty groups complete immediately)
        #pragma unroll
        for (int d = 0; d < DEPTH; d++) {
            int idx = d * TPB + tid;
            if (idx < n4) cp_async16(myslot0 + d * (TPB * 16), src + idx);
            cp_commit();
        }

        for (int k = 0; k < iters; k++) {
            cp_wait_most();                       // group k complete -> slot k%DEPTH ready
            int s = k & (DEPTH - 1);
            int idx = k * TPB + tid;
            if (idx < n4) {
                float4 v = s_pipe[s][tid];
                if (max4(v) > thresh) {
                    unsigned i0 = (unsigned)(start + 4 * idx);
                    if (v.x > thresh) push_hit(v.x, i0);
                    if (v.y > thresh) push_hit(v.y, i0 + 1);
                    if (v.z > thresh) push_hit(v.z, i0 + 2);
                    if (v.w > thresh) push_hit(v.w, i0 + 3);
                }
            }
            int nidx = (k + DEPTH) * TPB + tid;   // refill consumed slot
            if (nidx < n4) cp_async16(myslot0 + s * (TPB * 16), src + nidx);
            cp_commit();
        }
        cp_wait_all();                            // pipe smem idle before reuse

        // scalar tail (only if count % 4 != 0; never for this shape)
        int cnt4 = n4 << 2;
        int tail = count - cnt4;
        if (tid < tail) {
            float x = base[cnt4 + tid];
            if (x > thresh) push_hit(x, (unsigned)(start + cnt4 + tid));
        }
    }

    // ---- flush smem candidates to global ----
    __syncthreads();
    int cnt = min(s_cnt, SBUF);
    if (tid == 0) s_base = atomicAdd(&g_cnt[b], cnt);
    __syncthreads();
    int bs = s_base;
    for (int i2 = tid; i2 < cnt; i2 += TPB) {
        int p = bs + i2;
        if (p < CAP) g_cand[b * CAP + p] = s_buf[i2];
    }

    // ---- arrival: last slice CTA of this batch performs the selection ----
    __threadfence();
    __syncthreads();
    __shared__ int is_last;
    if (tid == 0)
        is_last = (atomicAdd(&g_done[b], 1) == gridDim.x - 1);
    __syncthreads();
    if (is_last) {
        __threadfence();   // acquire: other CTAs' candidate stores visible
        do_select(logits + (long long)b * N, segs, ts, out,
                  (unsigned long long*)&s_pipe[0][0], b, B, Q, C, K, N);
    }
}

extern "C" void kernel_launch(void* const* d_in, const int* in_sizes, int n_in,
                              void* d_out, int out_size) {
    const float* logits = (const float*)d_in[0];   // [B, Q, C] f32
    const float* segs   = (const float*)d_in[1];   // [B, Q, 2] f32
    const float* ts     = (const float*)d_in[2];   // [B] f32

    int B = in_sizes[2];
    int N = in_sizes[0] / B;          // Q * C
    int Q = in_sizes[1] / (2 * B);
    int C = N / Q;
    int K = 100;
    if (K > N) K = N;

    int per_cta = (((N + SLICES - 1) / SLICES) + 3) & ~3;
    dim3 grid(SLICES, B);
    k_main<<<grid, TPB>>>(logits, segs, ts, (float*)d_out, B, Q, C, K, per_cta, 2.8f);
}